// round 1
// baseline (speedup 1.0000x reference)
#include <cuda_runtime.h>
#include <cmath>

// Problem constants
static constexpr int B  = 4;
static constexpr int T  = 2048;
static constexpr int C  = 1024;
static constexpr int H  = 16;
static constexpr int HD = 64;          // C / H
static constexpr int M1  = B * T;      // 8192 rows for both GEMMs
static constexpr int N1  = 3 * C;      // 3072 qkv cols
static constexpr int BTC = B * T * C;  // 8388608

// Scratch (allocation-free rule: __device__ globals)
__device__ float g_q[BTC];    // q in [B,H,T,HD] layout
__device__ float g_att[BTC];  // attention output in [B,T,C] layout

// ---------------------------------------------------------------------------
// QKV GEMM: qkv = x @ Wqkv + bqkv, routed into g_q / kout / vout in
// [B,H,T,HD] layout. 64x64 tile, BK=16, 256 threads, 4x4 micro-tile.
// ---------------------------------------------------------------------------
__global__ __launch_bounds__(256) void qkv_gemm_kernel(
    const float* __restrict__ A,     // x  [M1, C]
    const float* __restrict__ W,     // Wqkv [C, N1]
    const float* __restrict__ bias,  // [N1]
    float* __restrict__ kout,        // [B*H, T, HD]
    float* __restrict__ vout)        // [B*H, T, HD]
{
    __shared__ float As[16][64];
    __shared__ float Bs[16][64];

    const int tid = threadIdx.x;
    const int tx  = tid & 15;
    const int ty  = tid >> 4;
    const int row0 = blockIdx.y * 64;
    const int col0 = blockIdx.x * 64;

    float acc[4][4] = {};

    for (int k0 = 0; k0 < C; k0 += 16) {
        #pragma unroll
        for (int i = tid; i < 1024; i += 256) {
            int mm = i >> 4, kk = i & 15;
            As[kk][mm] = A[(row0 + mm) * C + k0 + kk];
        }
        #pragma unroll
        for (int i = tid; i < 1024; i += 256) {
            int kk = i >> 6, nn = i & 63;
            Bs[kk][nn] = W[(k0 + kk) * N1 + col0 + nn];
        }
        __syncthreads();
        #pragma unroll
        for (int kk = 0; kk < 16; kk++) {
            float4 a4 = *reinterpret_cast<const float4*>(&As[kk][ty * 4]);
            float4 b4 = *reinterpret_cast<const float4*>(&Bs[kk][tx * 4]);
            float a[4] = {a4.x, a4.y, a4.z, a4.w};
            float b[4] = {b4.x, b4.y, b4.z, b4.w};
            #pragma unroll
            for (int i = 0; i < 4; i++)
                #pragma unroll
                for (int j = 0; j < 4; j++)
                    acc[i][j] = fmaf(a[i], b[j], acc[i][j]);
        }
        __syncthreads();
    }

    // Epilogue: add bias, route to q/k/v in [b,h,t,d] layout
    #pragma unroll
    for (int i = 0; i < 4; i++) {
        int m  = row0 + ty * 4 + i;
        int b_ = m / T;
        int t_ = m - b_ * T;
        #pragma unroll
        for (int j = 0; j < 4; j++) {
            int n = col0 + tx * 4 + j;
            float v = acc[i][j] + bias[n];
            int reg = n >> 10;        // 0=q, 1=k, 2=v
            int nn  = n & 1023;
            int h   = nn >> 6;
            int d   = nn & 63;
            int idx = ((b_ * H + h) * T + t_) * HD + d;
            if (reg == 0)      g_q[idx]  = v;
            else if (reg == 1) kout[idx] = v;
            else               vout[idx] = v;
        }
    }
}

// ---------------------------------------------------------------------------
// Flash-style causal attention. One block = 64 queries of one (b,h).
// 256 threads: thread t handles row r=t/4, output dims [16*(t%4), +16),
// and S columns c = 4*j + (t%4), j=0..15.
// ---------------------------------------------------------------------------
__global__ __launch_bounds__(256) void attn_kernel(
    const float* __restrict__ kbuf,  // [B*H, T, HD]
    const float* __restrict__ vbuf)  // [B*H, T, HD]
{
    extern __shared__ float sm[];
    float* Qs = sm;                 // 64 x 68
    float* Ks = Qs + 64 * 68;       // 64 x 68
    float* Ss = Ks + 64 * 68;       // 64 x 68
    float* Vs = Ss + 64 * 68;       // 64 x 64 (float4-aligned)

    const int qi  = blockIdx.x;     // query tile index
    const int bh  = blockIdx.y;     // b*H + h
    const int tid = threadIdx.x;
    const int r   = tid >> 2;       // 0..63 query row in tile
    const int l4  = tid & 3;
    const int dstart = l4 * 16;
    const float scale = 0.125f;     // hd^-0.5 = 64^-0.5

    const float* qptr = g_q  + ((long)bh * T + (long)qi * 64) * HD;
    const float* kptr = kbuf + (long)bh * T * HD;
    const float* vptr = vbuf + (long)bh * T * HD;

    // load Q tile
    for (int i = tid; i < 64 * HD; i += 256) {
        int rr = i >> 6, dd = i & 63;
        Qs[rr * 68 + dd] = qptr[rr * HD + dd];
    }

    float acc[16];
    #pragma unroll
    for (int j = 0; j < 16; j++) acc[j] = 0.f;
    float m = -1e30f, lsum = 0.f;
    const int qg = qi * 64 + r;

    for (int kb = 0; kb <= qi; kb++) {
        __syncthreads();  // protect prior-iter reads of K/V/S (and Q load on iter 0)
        for (int i = tid; i < 64 * HD; i += 256) {
            int rr = i >> 6, dd = i & 63;
            Ks[rr * 68 + dd] = kptr[(kb * 64 + rr) * HD + dd];
            Vs[rr * 64 + dd] = vptr[(kb * 64 + rr) * HD + dd];
        }
        __syncthreads();

        // S = Q K^T (this thread: row r, cols 4*j + l4)
        float s[16];
        #pragma unroll
        for (int j = 0; j < 16; j++) s[j] = 0.f;
        #pragma unroll
        for (int d4 = 0; d4 < 16; d4++) {
            float4 q4 = *reinterpret_cast<const float4*>(&Qs[r * 68 + d4 * 4]);
            #pragma unroll
            for (int j = 0; j < 16; j++) {
                int c = 4 * j + l4;
                float4 k4 = *reinterpret_cast<const float4*>(&Ks[c * 68 + d4 * 4]);
                s[j] += q4.x * k4.x + q4.y * k4.y + q4.z * k4.z + q4.w * k4.w;
            }
        }

        float tmax = -1e30f;
        #pragma unroll
        for (int j = 0; j < 16; j++) {
            int kg = kb * 64 + 4 * j + l4;
            s[j] = (kg <= qg) ? s[j] * scale : -1e30f;
            tmax = fmaxf(tmax, s[j]);
        }
        tmax = fmaxf(tmax, __shfl_xor_sync(0xffffffffu, tmax, 1));
        tmax = fmaxf(tmax, __shfl_xor_sync(0xffffffffu, tmax, 2));

        float mnew = fmaxf(m, tmax);
        float corr = expf(m - mnew);
        lsum *= corr;
        #pragma unroll
        for (int j = 0; j < 16; j++) acc[j] *= corr;

        float psum = 0.f;
        #pragma unroll
        for (int j = 0; j < 16; j++) {
            float p = expf(s[j] - mnew);
            psum += p;
            Ss[r * 68 + 4 * j + l4] = p;
        }
        lsum += psum;
        m = mnew;
        __syncthreads();  // P visible to whole row

        // O += P @ V  (this thread: row r, dims dstart..dstart+15)
        #pragma unroll 4
        for (int k = 0; k < 64; k++) {
            float p = Ss[r * 68 + k];
            const float4* vrow = reinterpret_cast<const float4*>(&Vs[k * 64 + dstart]);
            float4 v0 = vrow[0], v1 = vrow[1], v2 = vrow[2], v3 = vrow[3];
            acc[0]  = fmaf(p, v0.x, acc[0]);  acc[1]  = fmaf(p, v0.y, acc[1]);
            acc[2]  = fmaf(p, v0.z, acc[2]);  acc[3]  = fmaf(p, v0.w, acc[3]);
            acc[4]  = fmaf(p, v1.x, acc[4]);  acc[5]  = fmaf(p, v1.y, acc[5]);
            acc[6]  = fmaf(p, v1.z, acc[6]);  acc[7]  = fmaf(p, v1.w, acc[7]);
            acc[8]  = fmaf(p, v2.x, acc[8]);  acc[9]  = fmaf(p, v2.y, acc[9]);
            acc[10] = fmaf(p, v2.z, acc[10]); acc[11] = fmaf(p, v2.w, acc[11]);
            acc[12] = fmaf(p, v3.x, acc[12]); acc[13] = fmaf(p, v3.y, acc[13]);
            acc[14] = fmaf(p, v3.z, acc[14]); acc[15] = fmaf(p, v3.w, acc[15]);
        }
    }

    lsum += __shfl_xor_sync(0xffffffffu, lsum, 1);
    lsum += __shfl_xor_sync(0xffffffffu, lsum, 2);
    float inv = 1.f / lsum;

    const int b_ = bh / H;
    const int h_ = bh - b_ * H;
    float* optr = g_att + ((long)b_ * T + qg) * C + h_ * HD + dstart;
    #pragma unroll
    for (int j = 0; j < 16; j++) optr[j] = acc[j] * inv;
}

// ---------------------------------------------------------------------------
// Output projection: out = g_att @ Wout + bout   (8192 x 1024 x 1024)
// ---------------------------------------------------------------------------
__global__ __launch_bounds__(256) void out_gemm_kernel(
    const float* __restrict__ W,     // Wout [C, C]
    const float* __restrict__ bias,  // [C]
    float* __restrict__ out)         // [M1, C]
{
    __shared__ float As[16][64];
    __shared__ float Bs[16][64];

    const int tid = threadIdx.x;
    const int tx  = tid & 15;
    const int ty  = tid >> 4;
    const int row0 = blockIdx.y * 64;
    const int col0 = blockIdx.x * 64;

    float acc[4][4] = {};

    for (int k0 = 0; k0 < C; k0 += 16) {
        #pragma unroll
        for (int i = tid; i < 1024; i += 256) {
            int mm = i >> 4, kk = i & 15;
            As[kk][mm] = g_att[(row0 + mm) * C + k0 + kk];
        }
        #pragma unroll
        for (int i = tid; i < 1024; i += 256) {
            int kk = i >> 6, nn = i & 63;
            Bs[kk][nn] = W[(k0 + kk) * C + col0 + nn];
        }
        __syncthreads();
        #pragma unroll
        for (int kk = 0; kk < 16; kk++) {
            float4 a4 = *reinterpret_cast<const float4*>(&As[kk][ty * 4]);
            float4 b4 = *reinterpret_cast<const float4*>(&Bs[kk][tx * 4]);
            float a[4] = {a4.x, a4.y, a4.z, a4.w};
            float b[4] = {b4.x, b4.y, b4.z, b4.w};
            #pragma unroll
            for (int i = 0; i < 4; i++)
                #pragma unroll
                for (int j = 0; j < 4; j++)
                    acc[i][j] = fmaf(a[i], b[j], acc[i][j]);
        }
        __syncthreads();
    }

    #pragma unroll
    for (int i = 0; i < 4; i++) {
        int mrow = row0 + ty * 4 + i;
        #pragma unroll
        for (int j = 0; j < 4; j++) {
            int n = col0 + tx * 4 + j;
            out[mrow * C + n] = acc[i][j] + bias[n];
        }
    }
}

// ---------------------------------------------------------------------------
extern "C" void kernel_launch(void* const* d_in, const int* in_sizes, int n_in,
                              void* d_out, int out_size)
{
    const float* x    = (const float*)d_in[0];
    const float* Wqkv = (const float*)d_in[1];
    const float* bqkv = (const float*)d_in[2];
    const float* Wout = (const float*)d_in[3];
    const float* bout = (const float*)d_in[4];

    float* out  = (float*)d_out;          // [B,T,C]
    float* kout = out + BTC;              // [B,H,T,HD]
    float* vout = out + 2 * BTC;          // [B,H,T,HD]

    // 1) QKV projection (writes g_q + k/v output regions)
    qkv_gemm_kernel<<<dim3(N1 / 64, M1 / 64), 256>>>(x, Wqkv, bqkv, kout, vout);

    // 2) causal flash attention (reads g_q + k/v regions, writes g_att)
    const size_t smem = (size_t)(3 * 64 * 68 + 64 * 64) * sizeof(float);  // 68608 B
    cudaFuncSetAttribute(attn_kernel,
                         cudaFuncAttributeMaxDynamicSharedMemorySize, (int)smem);
    attn_kernel<<<dim3(T / 64, B * H), 256, smem>>>(kout, vout);

    // 3) output projection
    out_gemm_kernel<<<dim3(C / 64, M1 / 64), 256>>>(Wout, bout, out);
}

// round 3
// speedup vs baseline: 2.1862x; 2.1862x over previous
#include <cuda_runtime.h>
#include <cmath>

// Problem constants
static constexpr int B  = 4;
static constexpr int T  = 2048;
static constexpr int C  = 1024;
static constexpr int H  = 16;
static constexpr int HD = 64;          // C / H
static constexpr int M1  = B * T;      // 8192 rows for both GEMMs
static constexpr int N1  = 3 * C;      // 3072 qkv cols
static constexpr int BTC = B * T * C;  // 8388608

// Scratch (allocation-free rule: __device__ globals)
__device__ float g_q[BTC];    // q in [B,H,T,HD] layout (pre-scaled by 1/8)
__device__ float g_att[BTC];  // attention output in [B,T,C] layout

// ---------------------------------------------------------------------------
// QKV GEMM: 128x128 tile, BK=16, 256 threads, 8x8 microtile (2x2 quadrants of
// 4x4 at offsets {0,64}). Routes q/k/v into [B,H,T,HD] layout.
// ---------------------------------------------------------------------------
__global__ __launch_bounds__(256) void qkv_gemm_kernel(
    const float* __restrict__ A,     // x  [M1, C]
    const float* __restrict__ W,     // Wqkv [C, N1]
    const float* __restrict__ bias,  // [N1]
    float* __restrict__ kout,        // [B*H, T, HD]
    float* __restrict__ vout)        // [B*H, T, HD]
{
    __shared__ float As[16][132];    // transposed A tile, padded pitch
    __shared__ float Bs[16][128];

    const int tid = threadIdx.x;
    const int tx  = tid & 15;
    const int ty  = tid >> 4;
    const int row0 = blockIdx.y * 128;
    const int col0 = blockIdx.x * 128;

    float acc[8][8] = {};

    const int lr = tid >> 2;          // 0..63
    const int lk = (tid & 3) * 4;     // 0,4,8,12

    for (int k0 = 0; k0 < C; k0 += 16) {
        // load A tile transposed (rows lr and 64+lr)
        float4 a0 = *reinterpret_cast<const float4*>(&A[(row0 + lr) * C + k0 + lk]);
        float4 a1 = *reinterpret_cast<const float4*>(&A[(row0 + 64 + lr) * C + k0 + lk]);
        As[lk + 0][lr] = a0.x; As[lk + 1][lr] = a0.y;
        As[lk + 2][lr] = a0.z; As[lk + 3][lr] = a0.w;
        As[lk + 0][64 + lr] = a1.x; As[lk + 1][64 + lr] = a1.y;
        As[lk + 2][64 + lr] = a1.z; As[lk + 3][64 + lr] = a1.w;
        // load B tile (16 x 128), two float4 per thread, coalesced
        {
            int idx = tid * 4;
            int kk = idx >> 7, nn = idx & 127;
            *reinterpret_cast<float4*>(&Bs[kk][nn]) =
                *reinterpret_cast<const float4*>(&W[(k0 + kk) * N1 + col0 + nn]);
            int idx2 = idx + 1024;
            int k2 = idx2 >> 7, n2 = idx2 & 127;
            *reinterpret_cast<float4*>(&Bs[k2][n2]) =
                *reinterpret_cast<const float4*>(&W[(k0 + k2) * N1 + col0 + n2]);
        }
        __syncthreads();
        #pragma unroll
        for (int kk = 0; kk < 16; kk++) {
            float a[8], b[8];
            *reinterpret_cast<float4*>(a)     = *reinterpret_cast<const float4*>(&As[kk][ty * 4]);
            *reinterpret_cast<float4*>(a + 4) = *reinterpret_cast<const float4*>(&As[kk][64 + ty * 4]);
            *reinterpret_cast<float4*>(b)     = *reinterpret_cast<const float4*>(&Bs[kk][tx * 4]);
            *reinterpret_cast<float4*>(b + 4) = *reinterpret_cast<const float4*>(&Bs[kk][64 + tx * 4]);
            #pragma unroll
            for (int i = 0; i < 8; i++)
                #pragma unroll
                for (int j = 0; j < 8; j++)
                    acc[i][j] = fmaf(a[i], b[j], acc[i][j]);
        }
        __syncthreads();
    }

    // Epilogue: add bias, route to q/k/v in [b,h,t,d] layout. q pre-scaled.
    #pragma unroll
    for (int rh = 0; rh < 2; rh++) {
        #pragma unroll
        for (int i = 0; i < 4; i++) {
            int m  = row0 + rh * 64 + ty * 4 + i;
            int b_ = m >> 11;            // / T
            int t_ = m & 2047;
            #pragma unroll
            for (int ch = 0; ch < 2; ch++) {
                #pragma unroll
                for (int j = 0; j < 4; j++) {
                    int n = col0 + ch * 64 + tx * 4 + j;
                    float v = acc[rh * 4 + i][ch * 4 + j] + bias[n];
                    int reg = n >> 10;        // 0=q, 1=k, 2=v
                    int nn  = n & 1023;
                    int h   = nn >> 6;
                    int d   = nn & 63;
                    int idx = ((b_ * H + h) * T + t_) * HD + d;
                    if (reg == 0)      g_q[idx]  = v * 0.125f;
                    else if (reg == 1) kout[idx] = v;
                    else               vout[idx] = v;
                }
            }
        }
    }
}

// ---------------------------------------------------------------------------
// Flash attention, GEMM-ified. Block = 64 queries of one (b,h), 256 threads.
// Thread (tx,ty) owns a 4x4 microtile: rows ty*4..+3, cols tx*4..+3 of both
// S (keys) and O (dims).
// ---------------------------------------------------------------------------
__global__ __launch_bounds__(256) void attn_kernel(
    const float* __restrict__ kbuf,  // [B*H, T, HD]
    const float* __restrict__ vbuf)  // [B*H, T, HD]
{
    extern __shared__ float sm[];
    float* Qs = sm;                 // [64 d][68] : Qs[d*68 + r]   (Q^T, pre-scaled)
    float* Ks = Qs + 64 * 68;       // [64 d][68] : Ks[d*68 + c]   (K^T)
    float* Vs = Ks + 64 * 68;       // [64 k][68] : Vs[k*68 + d]
    float* Ps = Vs + 64 * 68;       // [64 k][68] : Ps[k*68 + r]   (P^T)

    const int qi  = blockIdx.x;
    const int bh  = blockIdx.y;
    const int tid = threadIdx.x;
    const int tx  = tid & 15;
    const int ty  = tid >> 4;

    const float* qptr = g_q  + ((long)bh * T + (long)qi * 64) * HD;
    const float* kptr = kbuf + (long)bh * T * HD;
    const float* vptr = vbuf + (long)bh * T * HD;

    // load Q tile transposed into Qs[d][r]
    for (int i = tid; i < 64 * 16; i += 256) {
        int r = i >> 4, d4 = (i & 15) * 4;
        float4 q = *reinterpret_cast<const float4*>(qptr + r * HD + d4);
        Qs[(d4 + 0) * 68 + r] = q.x; Qs[(d4 + 1) * 68 + r] = q.y;
        Qs[(d4 + 2) * 68 + r] = q.z; Qs[(d4 + 3) * 68 + r] = q.w;
    }

    float acc[4][4] = {};
    float mrow[4], lrow[4];
    #pragma unroll
    for (int i = 0; i < 4; i++) { mrow[i] = -1e30f; lrow[i] = 0.f; }

    for (int kb = 0; kb <= qi; kb++) {
        __syncthreads();  // prior-iter P/V reads done (also covers Q load, iter 0)
        // load K transposed + V direct
        for (int i = tid; i < 64 * 16; i += 256) {
            int r = i >> 4, d4 = (i & 15) * 4;
            float4 k = *reinterpret_cast<const float4*>(kptr + (kb * 64 + r) * HD + d4);
            Ks[(d4 + 0) * 68 + r] = k.x; Ks[(d4 + 1) * 68 + r] = k.y;
            Ks[(d4 + 2) * 68 + r] = k.z; Ks[(d4 + 3) * 68 + r] = k.w;
            float4 v = *reinterpret_cast<const float4*>(vptr + (kb * 64 + r) * HD + d4);
            *reinterpret_cast<float4*>(Vs + r * 68 + d4) = v;
        }
        __syncthreads();

        // S microtile = Q K^T (scale folded into Q)
        float s[4][4] = {};
        #pragma unroll 8
        for (int d = 0; d < 64; d++) {
            float4 a = *reinterpret_cast<const float4*>(Qs + d * 68 + ty * 4);
            float4 b = *reinterpret_cast<const float4*>(Ks + d * 68 + tx * 4);
            float av[4] = {a.x, a.y, a.z, a.w};
            float bv[4] = {b.x, b.y, b.z, b.w};
            #pragma unroll
            for (int i = 0; i < 4; i++)
                #pragma unroll
                for (int j = 0; j < 4; j++)
                    s[i][j] = fmaf(av[i], bv[j], s[i][j]);
        }

        // causal mask (only diagonal tile can be partially masked)
        if (kb == qi) {
            #pragma unroll
            for (int i = 0; i < 4; i++)
                #pragma unroll
                for (int j = 0; j < 4; j++)
                    if (tx * 4 + j > ty * 4 + i) s[i][j] = -1e30f;
        }

        // online softmax, per owned row (replicated across the 16-lane tx group)
        #pragma unroll
        for (int i = 0; i < 4; i++) {
            float tmax = fmaxf(fmaxf(s[i][0], s[i][1]), fmaxf(s[i][2], s[i][3]));
            tmax = fmaxf(tmax, __shfl_xor_sync(0xffffffffu, tmax, 1));
            tmax = fmaxf(tmax, __shfl_xor_sync(0xffffffffu, tmax, 2));
            tmax = fmaxf(tmax, __shfl_xor_sync(0xffffffffu, tmax, 4));
            tmax = fmaxf(tmax, __shfl_xor_sync(0xffffffffu, tmax, 8));
            float mnew = fmaxf(mrow[i], tmax);
            float corr = __expf(mrow[i] - mnew);
            lrow[i] *= corr;
            #pragma unroll
            for (int j = 0; j < 4; j++) acc[i][j] *= corr;
            float ps = 0.f;
            #pragma unroll
            for (int j = 0; j < 4; j++) {
                float p = __expf(s[i][j] - mnew);
                ps += p;
                Ps[(tx * 4 + j) * 68 + (ty * 4 + i)] = p;
            }
            ps += __shfl_xor_sync(0xffffffffu, ps, 1);
            ps += __shfl_xor_sync(0xffffffffu, ps, 2);
            ps += __shfl_xor_sync(0xffffffffu, ps, 4);
            ps += __shfl_xor_sync(0xffffffffu, ps, 8);
            lrow[i] += ps;
            mrow[i] = mnew;
        }
        __syncthreads();  // P^T visible

        // O += P @ V
        #pragma unroll 8
        for (int k = 0; k < 64; k++) {
            float4 p = *reinterpret_cast<const float4*>(Ps + k * 68 + ty * 4);
            float4 v = *reinterpret_cast<const float4*>(Vs + k * 68 + tx * 4);
            float pv[4] = {p.x, p.y, p.z, p.w};
            float vv[4] = {v.x, v.y, v.z, v.w};
            #pragma unroll
            for (int i = 0; i < 4; i++)
                #pragma unroll
                for (int j = 0; j < 4; j++)
                    acc[i][j] = fmaf(pv[i], vv[j], acc[i][j]);
        }
    }

    // write O
    const int b_ = bh >> 4;
    const int h_ = bh & 15;
    #pragma unroll
    for (int i = 0; i < 4; i++) {
        int qg = qi * 64 + ty * 4 + i;
        float inv = 1.f / lrow[i];
        float4 o;
        o.x = acc[i][0] * inv; o.y = acc[i][1] * inv;
        o.z = acc[i][2] * inv; o.w = acc[i][3] * inv;
        *reinterpret_cast<float4*>(g_att + ((long)(b_ * T + qg)) * C + h_ * 64 + tx * 4) = o;
    }
}

// ---------------------------------------------------------------------------
// Output projection: out = g_att @ Wout + bout   (8192 x 1024 x 1024)
// Same 128x128 scheme.
// ---------------------------------------------------------------------------
__global__ __launch_bounds__(256) void out_gemm_kernel(
    const float* __restrict__ W,     // Wout [C, C]
    const float* __restrict__ bias,  // [C]
    float* __restrict__ out)         // [M1, C]
{
    __shared__ float As[16][132];
    __shared__ float Bs[16][128];

    const int tid = threadIdx.x;
    const int tx  = tid & 15;
    const int ty  = tid >> 4;
    const int row0 = blockIdx.y * 128;
    const int col0 = blockIdx.x * 128;

    float acc[8][8] = {};

    const int lr = tid >> 2;
    const int lk = (tid & 3) * 4;

    for (int k0 = 0; k0 < C; k0 += 16) {
        float4 a0 = *reinterpret_cast<const float4*>(&g_att[(row0 + lr) * C + k0 + lk]);
        float4 a1 = *reinterpret_cast<const float4*>(&g_att[(row0 + 64 + lr) * C + k0 + lk]);
        As[lk + 0][lr] = a0.x; As[lk + 1][lr] = a0.y;
        As[lk + 2][lr] = a0.z; As[lk + 3][lr] = a0.w;
        As[lk + 0][64 + lr] = a1.x; As[lk + 1][64 + lr] = a1.y;
        As[lk + 2][64 + lr] = a1.z; As[lk + 3][64 + lr] = a1.w;
        {
            int idx = tid * 4;
            int kk = idx >> 7, nn = idx & 127;
            *reinterpret_cast<float4*>(&Bs[kk][nn]) =
                *reinterpret_cast<const float4*>(&W[(k0 + kk) * C + col0 + nn]);
            int idx2 = idx + 1024;
            int k2 = idx2 >> 7, n2 = idx2 & 127;
            *reinterpret_cast<float4*>(&Bs[k2][n2]) =
                *reinterpret_cast<const float4*>(&W[(k0 + k2) * C + col0 + n2]);
        }
        __syncthreads();
        #pragma unroll
        for (int kk = 0; kk < 16; kk++) {
            float a[8], b[8];
            *reinterpret_cast<float4*>(a)     = *reinterpret_cast<const float4*>(&As[kk][ty * 4]);
            *reinterpret_cast<float4*>(a + 4) = *reinterpret_cast<const float4*>(&As[kk][64 + ty * 4]);
            *reinterpret_cast<float4*>(b)     = *reinterpret_cast<const float4*>(&Bs[kk][tx * 4]);
            *reinterpret_cast<float4*>(b + 4) = *reinterpret_cast<const float4*>(&Bs[kk][64 + tx * 4]);
            #pragma unroll
            for (int i = 0; i < 8; i++)
                #pragma unroll
                for (int j = 0; j < 8; j++)
                    acc[i][j] = fmaf(a[i], b[j], acc[i][j]);
        }
        __syncthreads();
    }

    #pragma unroll
    for (int rh = 0; rh < 2; rh++) {
        #pragma unroll
        for (int i = 0; i < 4; i++) {
            int mrow = row0 + rh * 64 + ty * 4 + i;
            #pragma unroll
            for (int ch = 0; ch < 2; ch++) {
                int n = col0 + ch * 64 + tx * 4;
                float4 o;
                o.x = acc[rh * 4 + i][ch * 4 + 0] + bias[n + 0];
                o.y = acc[rh * 4 + i][ch * 4 + 1] + bias[n + 1];
                o.z = acc[rh * 4 + i][ch * 4 + 2] + bias[n + 2];
                o.w = acc[rh * 4 + i][ch * 4 + 3] + bias[n + 3];
                *reinterpret_cast<float4*>(&out[mrow * C + n]) = o;
            }
        }
    }
}

// ---------------------------------------------------------------------------
extern "C" void kernel_launch(void* const* d_in, const int* in_sizes, int n_in,
                              void* d_out, int out_size)
{
    const float* x    = (const float*)d_in[0];
    const float* Wqkv = (const float*)d_in[1];
    const float* bqkv = (const float*)d_in[2];
    const float* Wout = (const float*)d_in[3];
    const float* bout = (const float*)d_in[4];

    float* out  = (float*)d_out;          // [B,T,C]
    float* kout = out + BTC;              // [B,H,T,HD]
    float* vout = out + 2 * BTC;          // [B,H,T,HD]

    // 1) QKV projection
    qkv_gemm_kernel<<<dim3(N1 / 128, M1 / 128), 256>>>(x, Wqkv, bqkv, kout, vout);

    // 2) causal flash attention
    const size_t smem = (size_t)(4 * 64 * 68) * sizeof(float);  // 69632 B
    cudaFuncSetAttribute(attn_kernel,
                         cudaFuncAttributeMaxDynamicSharedMemorySize, (int)smem);
    attn_kernel<<<dim3(T / 64, B * H), 256, smem>>>(kout, vout);

    // 3) output projection
    out_gemm_kernel<<<dim3(C / 128, M1 / 128), 256>>>(Wout, bout, out);
}